// round 10
// baseline (speedup 1.0000x reference)
#include <cuda_runtime.h>
#include <math.h>

#define T 32768
#define D 1024
#define L 64                  // steps per chunk
#define NCHUNK (T / L)        // 512

#define ETA_MU  0.01f
#define ETA_VAR 0.02f

// Per-(chunk, col) scratch, [chunk][col] layout: 2MB each.
static __device__ float g_sum  [NCHUNK * D];
static __device__ float g_sumsq[NCHUNK * D];
static __device__ float g_smu  [NCHUNK * D];
static __device__ float g_A    [NCHUNK * D];
static __device__ float g_B    [NCHUNK * D];
static __device__ float g_muin [NCHUNK * D];
static __device__ float g_varin[NCHUNK * D];

// ---------------------------------------------------------------------------
// Pass B: one streaming read of x. 128-thread blocks, grid (NCHUNK, 2):
// 1024 CTAs -> up to 10 resident CTAs/SM (vs 3.5 at 512x256), doubling
// in-flight read streams per SM. Per (chunk, col): sum, sumsq (global stats),
// S_mu (zero-carry local mu scan), A, B with
//   S_var(mu_in) = A - B*mu_in + Cc*mu_in^2   (Cc data-independent).
// ---------------------------------------------------------------------------
__global__ void __launch_bounds__(128) pass_b(const float* __restrict__ x) {
    const int col4 = blockIdx.y * 128 + threadIdx.x;
    const int c    = blockIdx.x;
    const float4* __restrict__ xp =
        (const float4*)(x + (size_t)c * L * D) + col4;

    float4 sum   = {0,0,0,0}, sumsq = {0,0,0,0};
    float4 s     = {0,0,0,0};
    float4 A     = {0,0,0,0}, Bc    = {0,0,0,0};
    float  p     = 1.f;

    #pragma unroll 8
    for (int i = 0; i < L; i++) {
        float4 xv = __ldcs(&xp[(size_t)i * (D / 4)]);
        p *= (1.0f - ETA_MU);
        const float twoEtaP = (2.0f * ETA_VAR) * p;

        #define STEP(f)                                                     \
        {                                                                   \
            sum.f  += xv.f;                                                 \
            sumsq.f = fmaf(xv.f, xv.f, sumsq.f);                            \
            s.f     = fmaf(ETA_MU, xv.f - s.f, s.f);                        \
            float e = xv.f - s.f;                                           \
            A.f     = fmaf(1.0f - ETA_VAR, A.f,  ETA_VAR * e * e);          \
            Bc.f    = fmaf(1.0f - ETA_VAR, Bc.f, twoEtaP * e);              \
        }
        STEP(x) STEP(y) STEP(z) STEP(w)
        #undef STEP
    }
    const int idx4 = c * (D / 4) + col4;
    ((float4*)g_sum)  [idx4] = sum;
    ((float4*)g_sumsq)[idx4] = sumsq;
    ((float4*)g_smu)  [idx4] = s;
    ((float4*)g_A)    [idx4] = A;
    ((float4*)g_B)    [idx4] = Bc;
}

// ---------------------------------------------------------------------------
// Pass C: 64 blocks x 256 threads; block owns 16 columns.
//  1) float4-vectorized staging of A/B/S for its columns into SMEM (96KB)
//  2) parallel sum/sumsq reduction -> mu0, unbiased-std0 (torch.std quirk)
//  3) 16 threads run the serial 512-chunk carry recurrence from SMEM
// ---------------------------------------------------------------------------
#define CPB 16                          // columns per block
#define PC_THREADS 256
#define RED_GRP 16                      // chunk groups for the reduction

__global__ void __launch_bounds__(PC_THREADS) pass_c() {
    extern __shared__ float smem[];
    float* sA   = smem;                         // [NCHUNK][CPB]
    float* sB   = sA + NCHUNK * CPB;
    float* sS   = sB + NCHUNK * CPB;
    float* red  = sS + NCHUNK * CPB;            // [RED_GRP][CPB] x2

    const int tid  = threadIdx.x;
    const int col0 = blockIdx.x * CPB;
    const int c4pb = CPB / 4;                   // 4 float4 per chunk-row

    // --- stage A/B/S into smem, float4 granularity (coalesced) ---
    for (int i = tid; i < NCHUNK * c4pb; i += PC_THREADS) {
        const int chunk = i / c4pb;
        const int lc4   = i % c4pb;
        const int gidx4 = (chunk * D + col0) / 4 + lc4;
        const int sidx4 = i;
        ((float4*)sA)[sidx4] = __ldcs(&((const float4*)g_A)  [gidx4]);
        ((float4*)sB)[sidx4] = __ldcs(&((const float4*)g_B)  [gidx4]);
        ((float4*)sS)[sidx4] = __ldcs(&((const float4*)g_smu)[gidx4]);
    }

    // --- parallel sum/sumsq reduction ---
    {
        const int lc  = tid % CPB;
        const int grp = tid / CPB;
        const int cpg = NCHUNK / RED_GRP;
        float ps = 0.f, pq = 0.f;
        for (int c = grp * cpg; c < (grp + 1) * cpg; c++) {
            ps += __ldcs(&g_sum  [c * D + col0 + lc]);
            pq += __ldcs(&g_sumsq[c * D + col0 + lc]);
        }
        red[grp * CPB + lc]                  = ps;
        red[RED_GRP * CPB + grp * CPB + lc]  = pq;
    }
    __syncthreads();

    if (tid < CPB) {
        const int col = col0 + tid;

        float sum = 0.f, sumsq = 0.f;
        #pragma unroll
        for (int g = 0; g < RED_GRP; g++) {
            sum   += red[g * CPB + tid];
            sumsq += red[RED_GRP * CPB + g * CPB + tid];
        }
        const float mu0  = sum / (float)T;
        const float var0 = (sumsq - sum * mu0) / (float)(T - 1);
        const float std0 = sqrtf(fmaxf(var0, 0.0f));

        // Cc = sum_i 0.98^{L-1-i} * 0.02 * (0.99^{i+1})^2   (constant)
        float pv = 1.f, Cc = 0.f;
        const float q = (1.0f - ETA_MU) * (1.0f - ETA_MU);
        #pragma unroll
        for (int i = 0; i < L; i++) {
            pv *= q;
            Cc = fmaf(1.0f - ETA_VAR, Cc, ETA_VAR * pv);
        }
        const float dL  = (float)pow((double)(1.0f - ETA_MU),  (double)L);
        const float dvL = (float)pow((double)(1.0f - ETA_VAR), (double)L);

        float m = mu0, v = std0;
        #pragma unroll 8
        for (int c = 0; c < NCHUNK; c++) {
            const int si  = c * CPB + tid;
            const int gi  = c * D + col;
            g_muin [gi] = m;
            g_varin[gi] = v;
            float Sv = fmaf(Cc * m, m, fmaf(-sB[si], m, sA[si]));
            v = fmaf(dvL, v, Sv);
            m = fmaf(dL,  m, sS[si]);
        }
    }
}

#define PC_SMEM_BYTES ((3 * NCHUNK * CPB + 2 * RED_GRP * CPB) * (int)sizeof(float))

// ---------------------------------------------------------------------------
// Pass F: replay each chunk with exact carries; write norm, mu, var (float4,
// streaming loads/stores). out[0..T*D) = norm_x; out[T*D..) = [mu|var] 2D rows.
// ---------------------------------------------------------------------------
__global__ void __launch_bounds__(256) pass_f(const float* __restrict__ x,
                                              float* __restrict__ out) {
    const int col4 = threadIdx.x;
    const int c    = blockIdx.x;
    const int idx4 = c * (D / 4) + col4;

    float4 mu  = ((const float4*)g_muin) [idx4];
    float4 var = ((const float4*)g_varin)[idx4];

    const int t0 = c * L;
    const float4* __restrict__ xp  = (const float4*)(x   + (size_t)t0 * D) + col4;
    float4* __restrict__ nrm       = (float4*)(out + (size_t)t0 * D) + col4;
    float4* __restrict__ info      = (float4*)(out + (size_t)T * D
                                               + (size_t)t0 * (2 * D)) + col4;

    #pragma unroll 4
    for (int i = 0; i < L; i++) {
        float4 xv = __ldcs(&xp[(size_t)i * (D / 4)]);
        float4 nv;
        #define STEP(f)                                                     \
        {                                                                   \
            mu.f  = fmaf(ETA_MU, xv.f - mu.f, mu.f);                        \
            float d2 = xv.f - mu.f;                                         \
            var.f = fmaf(1.0f - ETA_VAR, var.f, ETA_VAR * d2 * d2);         \
            nv.f  = d2 * rsqrtf(var.f);                                     \
        }
        STEP(x) STEP(y) STEP(z) STEP(w)
        #undef STEP
        __stcs(&nrm [(size_t)i * (D / 4)],               nv);
        __stcs(&info[(size_t)i * (2 * D / 4)],           mu);
        __stcs(&info[(size_t)i * (2 * D / 4) + (D / 4)], var);
    }
}

extern "C" void kernel_launch(void* const* d_in, const int* in_sizes, int n_in,
                              void* d_out, int out_size) {
    const float* x = (const float*)d_in[0];
    float* out = (float*)d_out;
    (void)in_sizes; (void)n_in; (void)out_size;

    cudaFuncSetAttribute(pass_c, cudaFuncAttributeMaxDynamicSharedMemorySize,
                         PC_SMEM_BYTES);

    dim3 grid_b(NCHUNK, 2);
    pass_b<<<grid_b, 128>>>(x);
    pass_c<<<D / CPB, PC_THREADS, PC_SMEM_BYTES>>>();
    pass_f<<<NCHUNK, 256>>>(x, out);
}

// round 13
// speedup vs baseline: 1.0263x; 1.0263x over previous
#include <cuda_runtime.h>
#include <math.h>

#define T 32768
#define D 1024
#define L 64                  // steps per chunk
#define NCHUNK (T / L)        // 512

#define ETA_MU  0.01f
#define ETA_VAR 0.02f

// Per-(chunk, col) scratch, [chunk][col] layout: 2MB each.
static __device__ float g_sum  [NCHUNK * D];
static __device__ float g_sumsq[NCHUNK * D];
static __device__ float g_smu  [NCHUNK * D];
static __device__ float g_A    [NCHUNK * D];
static __device__ float g_B    [NCHUNK * D];
static __device__ float g_muin [NCHUNK * D];
static __device__ float g_varin[NCHUNK * D];

// ---------------------------------------------------------------------------
// Pass B: one streaming read of x (float4/thread = 4 cols; 256 thr = all of D).
// Per (chunk, col): sum, sumsq (global stats), S_mu (zero-carry local mu scan),
// A, B with  S_var(mu_in) = A - B*mu_in + Cc*mu_in^2  (Cc data-independent).
// ---------------------------------------------------------------------------
__global__ void __launch_bounds__(256) pass_b(const float* __restrict__ x) {
    const int col4 = threadIdx.x;
    const int c    = blockIdx.x;
    const float4* __restrict__ xp =
        (const float4*)(x + (size_t)c * L * D) + col4;

    float4 sum   = {0,0,0,0}, sumsq = {0,0,0,0};
    float4 s     = {0,0,0,0};
    float4 A     = {0,0,0,0}, Bc    = {0,0,0,0};
    float  p     = 1.f;

    #pragma unroll 8
    for (int i = 0; i < L; i++) {
        float4 xv = __ldcs(&xp[(size_t)i * (D / 4)]);
        p *= (1.0f - ETA_MU);
        const float twoEtaP = (2.0f * ETA_VAR) * p;

        #define STEP(f)                                                     \
        {                                                                   \
            sum.f  += xv.f;                                                 \
            sumsq.f = fmaf(xv.f, xv.f, sumsq.f);                            \
            s.f     = fmaf(ETA_MU, xv.f - s.f, s.f);                        \
            float e = xv.f - s.f;                                           \
            A.f     = fmaf(1.0f - ETA_VAR, A.f,  ETA_VAR * e * e);          \
            Bc.f    = fmaf(1.0f - ETA_VAR, Bc.f, twoEtaP * e);              \
        }
        STEP(x) STEP(y) STEP(z) STEP(w)
        #undef STEP
    }
    const int idx4 = c * (D / 4) + col4;
    ((float4*)g_sum)  [idx4] = sum;
    ((float4*)g_sumsq)[idx4] = sumsq;
    ((float4*)g_smu)  [idx4] = s;
    ((float4*)g_A)    [idx4] = A;
    ((float4*)g_B)    [idx4] = Bc;
}

// ---------------------------------------------------------------------------
// Pass C: 64 blocks x 256 threads; block owns 16 columns. PDL: constant
// prologue overlaps pass_b's drain; grid-dependency sync before scratch reads.
//  1) float4 staging of A/B/S into SMEM (96KB)
//  2) parallel sum/sumsq reduction -> mu0, unbiased-std0 (torch.std quirk)
//  3) 16 threads run the serial 512-chunk carry recurrence from SMEM
// ---------------------------------------------------------------------------
#define CPB 16                          // columns per block
#define PC_THREADS 256
#define RED_GRP 16                      // chunk groups for the reduction

__global__ void __launch_bounds__(PC_THREADS) pass_c() {
    extern __shared__ float smem[];
    float* sA   = smem;                         // [NCHUNK][CPB]
    float* sB   = sA + NCHUNK * CPB;
    float* sS   = sB + NCHUNK * CPB;
    float* red  = sS + NCHUNK * CPB;            // [RED_GRP][CPB] x2

    const int tid  = threadIdx.x;
    const int col0 = blockIdx.x * CPB;
    const int c4pb = CPB / 4;                   // 4 float4 per chunk-row

    // --- PDL prologue: data-independent constants while pass_b drains ---
    float pv = 1.f, Cc = 0.f;
    const float q = (1.0f - ETA_MU) * (1.0f - ETA_MU);
    #pragma unroll
    for (int i = 0; i < L; i++) {
        pv *= q;
        Cc = fmaf(1.0f - ETA_VAR, Cc, ETA_VAR * pv);
    }
    const float dL  = (float)pow((double)(1.0f - ETA_MU),  (double)L);
    const float dvL = (float)pow((double)(1.0f - ETA_VAR), (double)L);

    cudaGridDependencySynchronize();            // pass_b results now visible

    // --- stage A/B/S into smem, float4 granularity (coalesced) ---
    for (int i = tid; i < NCHUNK * c4pb; i += PC_THREADS) {
        const int chunk = i / c4pb;
        const int lc4   = i % c4pb;
        const int gidx4 = (chunk * D + col0) / 4 + lc4;
        ((float4*)sA)[i] = __ldcs(&((const float4*)g_A)  [gidx4]);
        ((float4*)sB)[i] = __ldcs(&((const float4*)g_B)  [gidx4]);
        ((float4*)sS)[i] = __ldcs(&((const float4*)g_smu)[gidx4]);
    }

    // --- parallel sum/sumsq reduction ---
    {
        const int lc  = tid % CPB;
        const int grp = tid / CPB;
        const int cpg = NCHUNK / RED_GRP;
        float ps = 0.f, pq = 0.f;
        for (int c = grp * cpg; c < (grp + 1) * cpg; c++) {
            ps += __ldcs(&g_sum  [c * D + col0 + lc]);
            pq += __ldcs(&g_sumsq[c * D + col0 + lc]);
        }
        red[grp * CPB + lc]                  = ps;
        red[RED_GRP * CPB + grp * CPB + lc]  = pq;
    }
    __syncthreads();

    if (tid < CPB) {
        const int col = col0 + tid;

        float sum = 0.f, sumsq = 0.f;
        #pragma unroll
        for (int g = 0; g < RED_GRP; g++) {
            sum   += red[g * CPB + tid];
            sumsq += red[RED_GRP * CPB + g * CPB + tid];
        }
        const float mu0  = sum / (float)T;
        const float var0 = (sumsq - sum * mu0) / (float)(T - 1);
        const float std0 = sqrtf(fmaxf(var0, 0.0f));

        float m = mu0, v = std0;
        #pragma unroll 8
        for (int c = 0; c < NCHUNK; c++) {
            const int si  = c * CPB + tid;
            const int gi  = c * D + col;
            g_muin [gi] = m;
            g_varin[gi] = v;
            float Sv = fmaf(Cc * m, m, fmaf(-sB[si], m, sA[si]));
            v = fmaf(dvL, v, Sv);
            m = fmaf(dL,  m, sS[si]);
        }
    }
}

#define PC_SMEM_BYTES ((3 * NCHUNK * CPB + 2 * RED_GRP * CPB) * (int)sizeof(float))

// ---------------------------------------------------------------------------
// Pass F helpers
// ---------------------------------------------------------------------------
__device__ __forceinline__ void gas_step(float4& mu, float4& var,
                                         const float4& xv, float4& nv) {
    #define STEP(f)                                                         \
    {                                                                       \
        mu.f  = fmaf(ETA_MU, xv.f - mu.f, mu.f);                            \
        float d2 = xv.f - mu.f;                                             \
        var.f = fmaf(1.0f - ETA_VAR, var.f, ETA_VAR * d2 * d2);             \
        nv.f  = d2 * rsqrtf(var.f);                                         \
    }
    STEP(x) STEP(y) STEP(z) STEP(w)
    #undef STEP
}

// ---------------------------------------------------------------------------
// Pass F: PDL — prefetch the first PF x-loads (independent of pass_c) so the
// 128MB read stream ramps while pass_c still runs; sync, then replay each
// chunk with exact carries; write norm, mu, var (float4, streaming stores).
// out[0..T*D) = norm_x; out[T*D..) = [mu|var] rows of 2D.
// ---------------------------------------------------------------------------
#define PF 4
__global__ void __launch_bounds__(256) pass_f(const float* __restrict__ x,
                                              float* __restrict__ out) {
    const int col4 = threadIdx.x;
    const int c    = blockIdx.x;
    const int idx4 = c * (D / 4) + col4;

    const int t0 = c * L;
    const float4* __restrict__ xp = (const float4*)(x + (size_t)t0 * D) + col4;

    float4 pre[PF];
    #pragma unroll
    for (int i = 0; i < PF; i++)
        pre[i] = __ldcs(&xp[(size_t)i * (D / 4)]);

    cudaGridDependencySynchronize();            // g_muin/g_varin now visible

    float4 mu  = ((const float4*)g_muin) [idx4];
    float4 var = ((const float4*)g_varin)[idx4];

    float4* __restrict__ nrm  = (float4*)(out + (size_t)t0 * D) + col4;
    float4* __restrict__ info = (float4*)(out + (size_t)T * D
                                          + (size_t)t0 * (2 * D)) + col4;

    #pragma unroll
    for (int i = 0; i < PF; i++) {
        float4 nv;
        gas_step(mu, var, pre[i], nv);
        __stcs(&nrm [(size_t)i * (D / 4)],               nv);
        __stcs(&info[(size_t)i * (2 * D / 4)],           mu);
        __stcs(&info[(size_t)i * (2 * D / 4) + (D / 4)], var);
    }
    #pragma unroll 4
    for (int i = PF; i < L; i++) {
        float4 xv = __ldcs(&xp[(size_t)i * (D / 4)]);
        float4 nv;
        gas_step(mu, var, xv, nv);
        __stcs(&nrm [(size_t)i * (D / 4)],               nv);
        __stcs(&info[(size_t)i * (2 * D / 4)],           mu);
        __stcs(&info[(size_t)i * (2 * D / 4) + (D / 4)], var);
    }
}

extern "C" void kernel_launch(void* const* d_in, const int* in_sizes, int n_in,
                              void* d_out, int out_size) {
    const float* x = (const float*)d_in[0];
    float* out = (float*)d_out;
    (void)in_sizes; (void)n_in; (void)out_size;

    cudaFuncSetAttribute(pass_c, cudaFuncAttributeMaxDynamicSharedMemorySize,
                         PC_SMEM_BYTES);

    pass_b<<<NCHUNK, 256>>>(x);

    // pass_c: PDL overlap with pass_b drain
    {
        cudaLaunchAttribute attr[1];
        attr[0].id = cudaLaunchAttributeProgrammaticStreamSerialization;
        attr[0].val.programmaticStreamSerializationAllowed = 1;
        cudaLaunchConfig_t cfg = {};
        cfg.gridDim  = dim3(D / CPB);
        cfg.blockDim = dim3(PC_THREADS);
        cfg.dynamicSmemBytes = PC_SMEM_BYTES;
        cfg.stream = 0;
        cfg.attrs = attr;
        cfg.numAttrs = 1;
        cudaLaunchKernelEx(&cfg, pass_c);
    }

    // pass_f: PDL overlap with pass_c (prefetches x before the dependency sync)
    {
        cudaLaunchAttribute attr[1];
        attr[0].id = cudaLaunchAttributeProgrammaticStreamSerialization;
        attr[0].val.programmaticStreamSerializationAllowed = 1;
        cudaLaunchConfig_t cfg = {};
        cfg.gridDim  = dim3(NCHUNK);
        cfg.blockDim = dim3(256);
        cfg.dynamicSmemBytes = 0;
        cfg.stream = 0;
        cfg.attrs = attr;
        cfg.numAttrs = 1;
        cudaLaunchKernelEx(&cfg, pass_f, x, out);
    }
}